// round 1
// baseline (speedup 1.0000x reference)
#include <cuda_runtime.h>
#include <cstdint>

// Space-to-depth k=2: in [32, 224, 224, 64] f32 -> out [32, 112, 112, 256]
// out[b, ho, wo, kh*128 + kw*64 + c] = in[b, 2*ho+kh, 2*wo+kw, c]
//
// Vectorized as float4. Output float4 index t decomposes as:
//   c4   = t % 64          (64 float4s = 256 output channels)
//   wo   = (t / 64) % 112
//   ho   = (t / 64 / 112) % 112
//   b    =  t / (64*112*112)
// and c4 = kh*32 + kw*16 + ci4  (ci4 in [0,16) = input channel float4)
// input float4 index = ((b*224 + 2*ho+kh)*224 + 2*wo+kw)*16 + ci4
//
// A warp of 32 consecutive t's covers ci4 0..15 for kw=0 then kw=1 (fixed kh),
// i.e. two 256B contiguous input segments -> fully coalesced loads and stores.

static constexpr int B  = 32;
static constexpr int H  = 224;
static constexpr int W  = 224;
static constexpr int C4 = 16;           // 64 channels / 4
static constexpr int HO = 112;
static constexpr int WO = 112;
static constexpr long long TOTAL4 = (long long)B * HO * WO * 64;  // output float4 count

__global__ void __launch_bounds__(256, 8)
s2d_kernel(const float4* __restrict__ in, float4* __restrict__ out)
{
    long long t = (long long)blockIdx.x * blockDim.x + threadIdx.x;
    if (t >= TOTAL4) return;

    int c4  = (int)(t & 63);              // 0..63
    long long r = t >> 6;                 // b*HO*WO + ho*WO + wo
    int wo  = (int)(r % WO);
    long long r2 = r / WO;
    int ho  = (int)(r2 % HO);
    int b   = (int)(r2 / HO);

    int kh  = c4 >> 5;                    // 0..1
    int kw  = (c4 >> 4) & 1;              // 0..1
    int ci4 = c4 & 15;                    // 0..15

    int hi = 2 * ho + kh;
    int wi = 2 * wo + kw;

    long long in_idx = (((long long)b * H + hi) * W + wi) * C4 + ci4;
    out[t] = in[in_idx];
}

extern "C" void kernel_launch(void* const* d_in, const int* in_sizes, int n_in,
                              void* d_out, int out_size)
{
    (void)in_sizes; (void)n_in; (void)out_size;
    const float4* in  = (const float4*)d_in[0];
    float4*       out = (float4*)d_out;

    const int threads = 256;
    const long long blocks = (TOTAL4 + threads - 1) / threads;  // 100352
    s2d_kernel<<<(unsigned)blocks, threads>>>(in, out);
}

// round 4
// speedup vs baseline: 1.0470x; 1.0470x over previous
#include <cuda_runtime.h>
#include <cstdint>

// Space-to-depth k=2: in [32, 224, 224, 64] f32 -> out [32, 112, 112, 256]
// out[b, ho, wo, kh*128 + kw*64 + c] = in[b, 2*ho+kh, 2*wo+kw, c]
//
// float4-vectorized gather. Output float4 index t:
//   c4 = t % 64 = kh*32 + kw*16 + ci4 ; r = t/64 = ((b*112)+ho)*112 + wo
//   in float4 idx = (((b*224 + 2*ho+kh)*224) + 2*wo+kw)*16 + ci4
// Warp of 32 consecutive t -> one contiguous 512B input segment and one
// contiguous 512B output segment (fully coalesced both directions).
//
// R2: 4 items per thread strided by blockDim (stride 256 -> c4 invariant,
// r advances by 4), streaming cache hints (__ldcs/__stcs) to keep the
// one-pass 822MB stream from churning L2.

static constexpr int B  = 32;
static constexpr int H  = 224;
static constexpr int W  = 224;
static constexpr int C4 = 16;            // 64 channels / 4 floats
static constexpr int HO = 112;
static constexpr int WO = 112;
static constexpr long long TOTAL4 = (long long)B * HO * WO * 64;  // 25,690,112
static constexpr int THREADS = 256;
static constexpr int ITEMS   = 4;        // float4s per thread

__global__ void __launch_bounds__(THREADS, 8)
s2d_kernel(const float4* __restrict__ in, float4* __restrict__ out)
{
    long long t0 = (long long)blockIdx.x * (THREADS * ITEMS) + threadIdx.x;

    // c4 is identical for all ITEMS (stride 256 is a multiple of 64)
    int c4  = (int)(t0 & 63);
    int kh  = c4 >> 5;
    int kw  = (c4 >> 4) & 1;
    int ci4 = c4 & 15;

    long long in_idx[ITEMS];
    float4    v[ITEMS];

    // Gather phase: compute all addresses, issue all loads back-to-back (MLP=4)
#pragma unroll
    for (int j = 0; j < ITEMS; j++) {
        long long t = t0 + (long long)j * THREADS;
        long long r = t >> 6;                 // b*HO*WO + ho*WO + wo
        int wo = (int)(r % WO);
        long long r2 = r / WO;
        int ho = (int)(r2 % HO);
        int b  = (int)(r2 / HO);
        int hi = 2 * ho + kh;
        int wi = 2 * wo + kw;
        in_idx[j] = (((long long)b * H + hi) * W + wi) * C4 + ci4;
    }
#pragma unroll
    for (int j = 0; j < ITEMS; j++)
        v[j] = __ldcs(&in[in_idx[j]]);

#pragma unroll
    for (int j = 0; j < ITEMS; j++)
        __stcs(&out[t0 + (long long)j * THREADS], v[j]);
}

extern "C" void kernel_launch(void* const* d_in, const int* in_sizes, int n_in,
                              void* d_out, int out_size)
{
    (void)in_sizes; (void)n_in; (void)out_size;
    const float4* in  = (const float4*)d_in[0];
    float4*       out = (float4*)d_out;

    // TOTAL4 = 25,690,112 is exactly divisible by THREADS*ITEMS = 1024
    const long long blocks = TOTAL4 / (THREADS * ITEMS);   // 25088
    s2d_kernel<<<(unsigned)blocks, THREADS>>>(in, out);
}